// round 3
// baseline (speedup 1.0000x reference)
#include <cuda_runtime.h>
#include <cuda_bf16.h>

#define L_  1024
#define DM  1024
#define DI  2048
#define NS  16
#define DR  64
#define BB  2
#define CH  8
#define CT  (L_/CH)                 // 128 steps per chunk

typedef unsigned long long u64;

// ---------------- scratch (static device globals; no allocation) -------------
__device__ float g_hid_t [BB*DI*L_];   // hidden, (b, d, t)
__device__ float g_gate_t[BB*DI*L_];   // gate,   (b, d, t)
__device__ float g_ssm   [BB*L_*96];   // (b*t, 96): [0:64)=dt_pre, [64:80)=B, [80:96)=C
__device__ float g_dt_t  [BB*DI*L_];   // softplus(dt), (b, d, t)
__device__ float g_so_t  [BB*DI*L_];   // scan output pre-out_proj, (b, d, t)

__device__ __forceinline__ float softplusf(float x) {
    return x > 20.f ? x : log1pf(__expf(x));
}

__device__ __forceinline__ void ffma2(u64& acc, u64 a, u64 b) {
    asm("fma.rn.f32x2 %0, %1, %2, %0;" : "+l"(acc) : "l"(a), "l"(b));
}

// =============================================================================
//  Big GEMM: 128x128 tile, BK=16, 256 threads, 8x8 microtile, packed FFMA2.
//  As2 stores each A value duplicated: As2[k][2m]=As2[k][2m+1]=A[m][k].
// =============================================================================
#define AS2_LD 268   // row stride (floats): 16B-aligned rows, 2-way max STS conflict

// GEMM1: hidden/gate = x @ w_in^T, transposed-split write into (b,d,t) layout
__global__ __launch_bounds__(256, 2)
void gemm_in(const float* __restrict__ A, const float* __restrict__ W)
{
    __shared__ __align__(16) float As2[16][AS2_LD];
    __shared__ __align__(16) float Bs [16][132];
    const int K = DM;
    int tid = threadIdx.x;
    int n0 = blockIdx.x * 128;
    int m0 = blockIdx.y * 128;
    int tx = tid & 15, ty = tid >> 4;
    u64 acc2[8][4] = {};

    for (int k0 = 0; k0 < K; k0 += 16) {
        #pragma unroll
        for (int r = 0; r < 2; r++) {
            int li = tid + r * 256;
            int m  = li >> 2;
            int kq = (li & 3) * 4;
            float4 fa = *(const float4*)&A[(size_t)(m0 + m) * K + k0 + kq];
            *(float2*)&As2[kq+0][2*m] = make_float2(fa.x, fa.x);
            *(float2*)&As2[kq+1][2*m] = make_float2(fa.y, fa.y);
            *(float2*)&As2[kq+2][2*m] = make_float2(fa.z, fa.z);
            *(float2*)&As2[kq+3][2*m] = make_float2(fa.w, fa.w);
            float4 fb = *(const float4*)&W[(size_t)(n0 + m) * K + k0 + kq];
            Bs[kq+0][m] = fb.x; Bs[kq+1][m] = fb.y; Bs[kq+2][m] = fb.z; Bs[kq+3][m] = fb.w;
        }
        __syncthreads();
        #pragma unroll
        for (int k = 0; k < 16; k++) {
            const u64* ap = (const u64*)&As2[k][ty * 16];
            const u64* bp = (const u64*)&Bs [k][tx * 8];
            u64 ad[8], bd[4];
            #pragma unroll
            for (int i = 0; i < 8; i++) ad[i] = ap[i];
            #pragma unroll
            for (int j = 0; j < 4; j++) bd[j] = bp[j];
            #pragma unroll
            for (int i = 0; i < 8; i++)
                #pragma unroll
                for (int j = 0; j < 4; j++)
                    ffma2(acc2[i][j], ad[i], bd[j]);
        }
        __syncthreads();
    }

    float acc[8][8];
    #pragma unroll
    for (int i = 0; i < 8; i++)
        #pragma unroll
        for (int j = 0; j < 4; j++) {
            float2 v = *(float2*)&acc2[i][j];
            acc[i][2*j] = v.x; acc[i][2*j+1] = v.y;
        }

    int bb = m0 >> 10;              // m-tile lies entirely in one batch
    int t0 = (m0 & 1023) + ty * 8;
    float* dst = (n0 < DI) ? g_hid_t : g_gate_t;
    int nb = (n0 < DI) ? n0 : n0 - DI;
    #pragma unroll
    for (int j = 0; j < 8; j++) {
        int col = nb + tx * 8 + j;
        size_t base = ((size_t)bb * DI + col) * L_ + t0;
        *(float4*)&dst[base]     = make_float4(acc[0][j], acc[1][j], acc[2][j], acc[3][j]);
        *(float4*)&dst[base + 4] = make_float4(acc[4][j], acc[5][j], acc[6][j], acc[7][j]);
    }
}

// GEMM5: out = so @ w_out^T, A read K-major from g_so_t, row-major write
__global__ __launch_bounds__(256, 2)
void gemm_out(const float* __restrict__ W, float* __restrict__ Out)
{
    __shared__ __align__(16) float As2[16][AS2_LD];
    __shared__ __align__(16) float Bs [16][132];
    const int K = DI;   // 2048
    const int N = DM;   // 1024
    int tid = threadIdx.x;
    int n0 = blockIdx.x * 128;
    int m0 = blockIdx.y * 128;
    int bb = m0 >> 10;
    int t0 = m0 & 1023;
    int tx = tid & 15, ty = tid >> 4;
    u64 acc2[8][4] = {};

    for (int k0 = 0; k0 < K; k0 += 16) {
        // A: K-major (b, k, t) — coalesced float4 along t, store duplicated
        #pragma unroll
        for (int r = 0; r < 2; r++) {
            int li = tid + r * 256;
            int m4 = (li & 31) * 4;
            int k  = li >> 5;
            float4 fa = *(const float4*)&g_so_t[((size_t)bb * DI + k0 + k) * L_ + t0 + m4];
            *(float4*)&As2[k][2*m4]     = make_float4(fa.x, fa.x, fa.y, fa.y);
            *(float4*)&As2[k][2*m4 + 4] = make_float4(fa.z, fa.z, fa.w, fa.w);
        }
        // W: row-major (N, K) — transpose on load
        #pragma unroll
        for (int r = 0; r < 2; r++) {
            int li = tid + r * 256;
            int n  = li >> 2;
            int kq = (li & 3) * 4;
            float4 fb = *(const float4*)&W[(size_t)(n0 + n) * K + k0 + kq];
            Bs[kq+0][n] = fb.x; Bs[kq+1][n] = fb.y; Bs[kq+2][n] = fb.z; Bs[kq+3][n] = fb.w;
        }
        __syncthreads();
        #pragma unroll
        for (int k = 0; k < 16; k++) {
            const u64* ap = (const u64*)&As2[k][ty * 16];
            const u64* bp = (const u64*)&Bs [k][tx * 8];
            u64 ad[8], bd[4];
            #pragma unroll
            for (int i = 0; i < 8; i++) ad[i] = ap[i];
            #pragma unroll
            for (int j = 0; j < 4; j++) bd[j] = bp[j];
            #pragma unroll
            for (int i = 0; i < 8; i++)
                #pragma unroll
                for (int j = 0; j < 4; j++)
                    ffma2(acc2[i][j], ad[i], bd[j]);
        }
        __syncthreads();
    }

    #pragma unroll
    for (int i = 0; i < 8; i++) {
        size_t row = (size_t)(m0 + ty * 8 + i) * N + n0 + tx * 8;
        float2 v0 = *(float2*)&acc2[i][0];
        float2 v1 = *(float2*)&acc2[i][1];
        float2 v2 = *(float2*)&acc2[i][2];
        float2 v3 = *(float2*)&acc2[i][3];
        *(float4*)&Out[row]     = make_float4(v0.x, v0.y, v1.x, v1.y);
        *(float4*)&Out[row + 4] = make_float4(v2.x, v2.y, v3.x, v3.y);
    }
}

// =============================================================================
//  Small GEMM (64x64, 4x4 micro) for x_proj / dt_proj
// =============================================================================
template<int EPI, bool AKMAJ, int ASRC>
__global__ __launch_bounds__(256)
void gemm_k(const float* __restrict__ W, int M, int N, int K, int lda,
            const float* __restrict__ bias)
{
    const float* A = (ASRC == 1) ? g_hid_t : g_ssm;

    __shared__ __align__(16) float As[16][68];
    __shared__ __align__(16) float Bs[16][68];

    int tid = threadIdx.x;
    int n0 = blockIdx.x * 64;
    int m0 = blockIdx.y * 64;
    int tr = tid >> 4;
    int tc = tid & 15;
    float acc[4][4] = {};

    for (int k0 = 0; k0 < K; k0 += 16) {
        if (AKMAJ) {
            #pragma unroll
            for (int i = 0; i < 4; i++) {
                int li = tid + i * 256;
                int m = li & 63, k = li >> 6;
                int gm = m0 + m;
                As[k][m] = A[(((gm >> 10) * K) + k0 + k) * L_ + (gm & 1023)];
            }
        } else {
            #pragma unroll
            for (int i = 0; i < 4; i++) {
                int li = tid + i * 256;
                int k = li & 15, m = li >> 4;
                As[k][m] = A[(m0 + m) * lda + k0 + k];
            }
        }
        #pragma unroll
        for (int i = 0; i < 4; i++) {
            int li = tid + i * 256;
            int k = li & 15, n = li >> 4;
            int gn = n0 + n;
            Bs[k][n] = (gn < N) ? W[gn * K + k0 + k] : 0.f;
        }
        __syncthreads();
        #pragma unroll
        for (int k = 0; k < 16; k++) {
            float4 av = *(const float4*)&As[k][tr * 4];
            float4 bv = *(const float4*)&Bs[k][tc * 4];
            float a4[4] = {av.x, av.y, av.z, av.w};
            float b4[4] = {bv.x, bv.y, bv.z, bv.w};
            #pragma unroll
            for (int i = 0; i < 4; i++)
                #pragma unroll
                for (int j = 0; j < 4; j++)
                    acc[i][j] = fmaf(a4[i], b4[j], acc[i][j]);
        }
        __syncthreads();
    }

    if (EPI == 1) {
        #pragma unroll
        for (int i = 0; i < 4; i++) {
            int gm = m0 + tr * 4 + i;
            #pragma unroll
            for (int j = 0; j < 4; j++) {
                int gn = n0 + tc * 4 + j;
                if (gn < N) g_ssm[gm * 96 + gn] = acc[i][j];
            }
        }
    } else {
        // dt_proj: softplus(acc + bias), store (b,d,t) with float4 along t
        int bb = m0 >> 10;
        int t0 = (m0 & 1023) + tr * 4;
        #pragma unroll
        for (int j = 0; j < 4; j++) {
            int gn = n0 + tc * 4 + j;
            float bz = bias[gn];
            float4 v;
            v.x = softplusf(acc[0][j] + bz);
            v.y = softplusf(acc[1][j] + bz);
            v.z = softplusf(acc[2][j] + bz);
            v.w = softplusf(acc[3][j] + bz);
            *(float4*)&g_dt_t[((size_t)bb * DI + gn) * L_ + t0] = v;
        }
    }
}

// =============================================================================
//  Fused chunked bidirectional scan: block = one (b,d), 8 warps = 8 chunks.
//  fwd: s_t = a_t s_{t-1} + u_t ; bwd: s_t = a_{t+1} s_{t+1} + u_t (a_L := 0)
// =============================================================================
__global__ __launch_bounds__(256)
void scan_fused(const float* __restrict__ A_log, const float* __restrict__ Dp)
{
    __shared__ float sP  [2][NS][CH];
    __shared__ float sS  [2][NS][CH];
    __shared__ float sCin[2][NS][CH];
    __shared__ float y[L_];

    int bd   = blockIdx.x;
    int b    = bd >> 11;
    int d    = bd & (DI - 1);
    int c    = threadIdx.x >> 5;          // chunk
    int lane = threadIdx.x & 31;
    int n    = lane & 15;
    bool fw  = lane < 16;
    int dir  = fw ? 0 : 1;

    size_t off = ((size_t)b * DI + d) * L_;
    const float* dtp = g_dt_t  + off;
    const float* hp  = g_hid_t + off;
    const float* ssm = g_ssm   + (size_t)b * L_ * 96;
    float An = -__expf(A_log[d * NS + n]);

    for (int t = threadIdx.x; t < L_; t += 256) y[t] = 0.f;

    int lo = c * CT, hi = lo + CT - 1;
    int sdelta = fw ? 96 : -96;

    // -------- phase A: chunk operator (P, S) --------
    {
        float s = 0.f, P = 1.f;
        float pb = (hi + 1 < L_) ? __expf(An * dtp[hi + 1]) : 0.f;
        const float* sp = ssm + (fw ? lo : hi) * 96 + 64 + n;
        for (int i0 = 0; i0 < CT; i0 += 4) {
            int tb = fw ? lo + i0 : hi - i0 - 3;
            float4 dt4 = *(const float4*)&dtp[tb];
            float4 h4  = *(const float4*)&hp[tb];
            float dts[4] = {dt4.x, dt4.y, dt4.z, dt4.w};
            float hs4[4] = {h4.x, h4.y, h4.z, h4.w};
            #pragma unroll
            for (int j = 0; j < 4; j++) {
                int jj = fw ? j : 3 - j;
                float dtv = dts[jj], h = hs4[jj];
                float a  = __expf(An * dtv);
                float Bv = sp[0];
                float u  = dtv * Bv * h;
                float coef = fw ? a : pb;
                s = fmaf(coef, s, u);
                P *= coef;
                pb = a;
                sp += sdelta;
            }
        }
        sP[dir][n][c] = P;
        sS[dir][n][c] = s;
    }
    __syncthreads();

    // -------- combine: 32 threads, one (dir, n) chain each --------
    if (threadIdx.x < 32) {
        int dr = threadIdx.x >> 4, nn = threadIdx.x & 15;
        float cin = 0.f;
        if (dr == 0) {
            #pragma unroll
            for (int cc = 0; cc < CH; cc++) {
                sCin[0][nn][cc] = cin;
                cin = fmaf(sP[0][nn][cc], cin, sS[0][nn][cc]);
            }
        } else {
            #pragma unroll
            for (int cc = CH - 1; cc >= 0; cc--) {
                sCin[1][nn][cc] = cin;
                cin = fmaf(sP[1][nn][cc], cin, sS[1][nn][cc]);
            }
        }
    }
    __syncthreads();

    // -------- phase C: seeded re-scan + C-reduction --------
    {
        float s  = sCin[dir][n][c];
        float pb = (hi + 1 < L_) ? __expf(An * dtp[hi + 1]) : 0.f;
        const float* sp = ssm + (fw ? lo : hi) * 96 + 64 + n;
        int t = fw ? lo : hi;
        int tstep = fw ? 1 : -1;
        for (int i0 = 0; i0 < CT; i0 += 4) {
            int tb = fw ? lo + i0 : hi - i0 - 3;
            float4 dt4 = *(const float4*)&dtp[tb];
            float4 h4  = *(const float4*)&hp[tb];
            float dts[4] = {dt4.x, dt4.y, dt4.z, dt4.w};
            float hs4[4] = {h4.x, h4.y, h4.z, h4.w};
            #pragma unroll
            for (int j = 0; j < 4; j++) {
                int jj = fw ? j : 3 - j;
                float dtv = dts[jj], h = hs4[jj];
                float a  = __expf(An * dtv);
                float Bv = sp[0];
                float Cv = sp[16];
                float u  = dtv * Bv * h;
                float coef = fw ? a : pb;
                s = fmaf(coef, s, u);
                float base = fw ? s : (s - u);   // bwd contributes s_bwd - u
                float contrib = Cv * base;
                pb = a;
                sp += sdelta;

                contrib += __shfl_xor_sync(0xffffffffu, contrib, 8);
                contrib += __shfl_xor_sync(0xffffffffu, contrib, 4);
                contrib += __shfl_xor_sync(0xffffffffu, contrib, 2);
                contrib += __shfl_xor_sync(0xffffffffu, contrib, 1);
                if (n == 0) y[t] += contrib;     // fwd/bwd hit disjoint t per step
                t += tstep;
            }
        }
    }
    __syncthreads();

    // -------- epilogue: gating, vectorized --------
    {
        float Dv = Dp[d];
        int t4 = threadIdx.x * 4;
        float4 g4 = *(const float4*)&g_gate_t[off + t4];
        float4 h4 = *(const float4*)&hp[t4];
        float4 y4 = *(const float4*)&y[t4];
        float4 o;
        o.x = (1.3f * y4.x + h4.x * Dv) * (g4.x / (1.f + __expf(-g4.x)));
        o.y = (1.3f * y4.y + h4.y * Dv) * (g4.y / (1.f + __expf(-g4.y)));
        o.z = (1.3f * y4.z + h4.z * Dv) * (g4.z / (1.f + __expf(-g4.z)));
        o.w = (1.3f * y4.w + h4.w * Dv) * (g4.w / (1.f + __expf(-g4.w)));
        *(float4*)&g_so_t[off + t4] = o;
    }
}

// ---------------- launch -----------------------------------------------------
extern "C" void kernel_launch(void* const* d_in, const int* in_sizes, int n_in,
                              void* d_out, int out_size)
{
    const float* x      = (const float*)d_in[0];  // (2,1024,1024)
    const float* w_in   = (const float*)d_in[1];  // (4096,1024)
    const float* w_x    = (const float*)d_in[2];  // (96,2048)
    const float* w_dt   = (const float*)d_in[3];  // (2048,64)
    const float* b_dt   = (const float*)d_in[4];  // (2048,)
    const float* A_log  = (const float*)d_in[5];  // (2048,16)
    const float* Dvec   = (const float*)d_in[6];  // (2048,)
    const float* w_out  = (const float*)d_in[7];  // (1024,2048)
    float* out = (float*)d_out;                   // (2,1024,1024)

    const int M = BB * L_;  // 2048

    // 1) in_proj (packed-FMA GEMM)
    gemm_in<<<dim3(4096 / 128, M / 128), 256>>>(x, w_in);
    // 2) x_proj: hidden (K-major) @ (96x2048)^T -> g_ssm
    gemm_k<1, true, 1><<<dim3(2, M / 64), 256>>>(w_x, M, 96, DI, 0, nullptr);
    // 3) dt_proj: ssm[:, :64] @ (2048x64)^T + b, softplus -> g_dt_t
    gemm_k<2, false, 2><<<dim3(DI / 64, M / 64), 256>>>(w_dt, M, DI, DR, 96, b_dt);
    // 4) fused chunked bidirectional scan
    scan_fused<<<BB * DI, 256>>>(A_log, Dvec);
    // 5) out_proj (packed-FMA GEMM)
    gemm_out<<<dim3(DM / 128, M / 128), 256>>>(w_out, out);
}

// round 6
// speedup vs baseline: 1.2396x; 1.2396x over previous
#include <cuda_runtime.h>
#include <cuda_bf16.h>

#define L_  1024
#define DM  1024
#define DI  2048
#define NS  16
#define DR  64
#define BB  2
#define CH  8
#define CT  (L_/CH)                 // 128 steps per chunk

typedef unsigned long long u64;

// ---------------- scratch (static device globals; no allocation) -------------
__device__ float g_hid_t [BB*DI*L_];   // hidden, (b, d, t)
__device__ float g_gate_t[BB*DI*L_];   // gate,   (b, d, t)
__device__ float g_ssm   [BB*L_*96];   // (b*t, 96): [0:64)=dt_pre, [64:80)=B, [80:96)=C
__device__ float g_dt_t  [BB*DI*L_];   // softplus(dt), (b, d, t)
__device__ float g_so_t  [BB*DI*L_];   // scan output pre-out_proj, (b, d, t)

__device__ __forceinline__ float softplusf(float x) {
    return x > 20.f ? x : log1pf(__expf(x));
}
__device__ __forceinline__ void ffma2(u64& acc, u64 a, u64 b) {
    asm("fma.rn.f32x2 %0, %1, %2, %0;" : "+l"(acc) : "l"(a), "l"(b));
}
__device__ __forceinline__ u64 dup2(float x) {
    u64 r; asm("mov.b64 %0, {%1, %1};" : "=l"(r) : "f"(x)); return r;
}

// =============================================================================
//  Big GEMM: 128x128 tile, BK=16, 256 threads, 8x8 microtile (4+4 split halves)
//  Packed FFMA2: A pairs natural (consecutive m), B duplicated in registers.
// =============================================================================

__device__ __forceinline__ void mma_step(const float* As_k, const float* Bs_k,
                                         int tx, int ty, u64 acc2[4][8])
{
    u64 ap[4];
    ap[0] = ((const u64*)&As_k[ty*4])[0];
    ap[1] = ((const u64*)&As_k[ty*4])[1];
    ap[2] = ((const u64*)&As_k[64 + ty*4])[0];
    ap[3] = ((const u64*)&As_k[64 + ty*4])[1];
    float4 b0 = *(const float4*)&Bs_k[tx*4];
    float4 b1 = *(const float4*)&Bs_k[64 + tx*4];
    u64 bd[8];
    bd[0] = dup2(b0.x); bd[1] = dup2(b0.y); bd[2] = dup2(b0.z); bd[3] = dup2(b0.w);
    bd[4] = dup2(b1.x); bd[5] = dup2(b1.y); bd[6] = dup2(b1.z); bd[7] = dup2(b1.w);
    #pragma unroll
    for (int ip = 0; ip < 4; ip++)
        #pragma unroll
        for (int j = 0; j < 8; j++)
            ffma2(acc2[ip][j], ap[ip], bd[j]);
}

// GEMM1: hidden/gate = x @ w_in^T, transposed-split write into (b,d,t) layout
__global__ __launch_bounds__(256, 2)
void gemm_in(const float* __restrict__ A, const float* __restrict__ W)
{
    __shared__ __align__(16) float As[16][132];
    __shared__ __align__(16) float Bs[16][132];
    const int K = DM;
    int tid = threadIdx.x;
    int n0 = blockIdx.x * 128;
    int m0 = blockIdx.y * 128;
    int tx = tid & 15, ty = tid >> 4;
    u64 acc2[4][8] = {};

    for (int k0 = 0; k0 < K; k0 += 16) {
        #pragma unroll
        for (int r = 0; r < 2; r++) {
            int li = tid + r * 256;
            int m  = li >> 2;
            int kq = (li & 3) * 4;
            float4 fa = *(const float4*)&A[(size_t)(m0 + m) * K + k0 + kq];
            As[kq+0][m] = fa.x; As[kq+1][m] = fa.y; As[kq+2][m] = fa.z; As[kq+3][m] = fa.w;
            float4 fb = *(const float4*)&W[(size_t)(n0 + m) * K + k0 + kq];
            Bs[kq+0][m] = fb.x; Bs[kq+1][m] = fb.y; Bs[kq+2][m] = fb.z; Bs[kq+3][m] = fb.w;
        }
        __syncthreads();
        #pragma unroll
        for (int k = 0; k < 16; k++)
            mma_step(As[k], Bs[k], tx, ty, acc2);
        __syncthreads();
    }

    int bb = m0 >> 10;              // m-tile lies entirely in one batch
    int t0 = m0 & 1023;
    float* dst = (n0 < DI) ? g_hid_t : g_gate_t;
    int nb = (n0 < DI) ? n0 : n0 - DI;
    #pragma unroll
    for (int j = 0; j < 8; j++) {
        int col = nb + ((j < 4) ? tx*4 + j : 64 + tx*4 + j - 4);
        size_t base = ((size_t)bb * DI + col) * L_ + t0;
        float2 p0 = *(float2*)&acc2[0][j];
        float2 p1 = *(float2*)&acc2[1][j];
        float2 p2 = *(float2*)&acc2[2][j];
        float2 p3 = *(float2*)&acc2[3][j];
        *(float4*)&dst[base + ty*4]      = make_float4(p0.x, p0.y, p1.x, p1.y);
        *(float4*)&dst[base + 64 + ty*4] = make_float4(p2.x, p2.y, p3.x, p3.y);
    }
}

// GEMM5: out = so @ w_out^T, A read K-major from g_so_t, row-major write
__global__ __launch_bounds__(256, 2)
void gemm_out(const float* __restrict__ W, float* __restrict__ Out)
{
    __shared__ __align__(16) float As[16][132];
    __shared__ __align__(16) float Bs[16][132];
    const int K = DI;   // 2048
    const int N = DM;   // 1024
    int tid = threadIdx.x;
    int n0 = blockIdx.x * 128;
    int m0 = blockIdx.y * 128;
    int bb = m0 >> 10;
    int t0 = m0 & 1023;
    int tx = tid & 15, ty = tid >> 4;
    u64 acc2[4][8] = {};

    for (int k0 = 0; k0 < K; k0 += 16) {
        // A: K-major (b, k, t) — coalesced float4 along t, vector STS
        #pragma unroll
        for (int r = 0; r < 2; r++) {
            int li = tid + r * 256;
            int m4 = (li & 31) * 4;
            int k  = li >> 5;
            float4 fa = *(const float4*)&g_so_t[((size_t)bb * DI + k0 + k) * L_ + t0 + m4];
            *(float4*)&As[k][m4] = fa;
        }
        // W: row-major (N, K) — transpose on load
        #pragma unroll
        for (int r = 0; r < 2; r++) {
            int li = tid + r * 256;
            int n  = li >> 2;
            int kq = (li & 3) * 4;
            float4 fb = *(const float4*)&W[(size_t)(n0 + n) * K + k0 + kq];
            Bs[kq+0][n] = fb.x; Bs[kq+1][n] = fb.y; Bs[kq+2][n] = fb.z; Bs[kq+3][n] = fb.w;
        }
        __syncthreads();
        #pragma unroll
        for (int k = 0; k < 16; k++)
            mma_step(As[k], Bs[k], tx, ty, acc2);
        __syncthreads();
    }

    #pragma unroll
    for (int ip = 0; ip < 4; ip++) {
        int r0 = (ip < 2) ? ty*4 + 2*ip : 64 + ty*4 + 2*(ip - 2);
        float2 q0 = *(float2*)&acc2[ip][0];
        float2 q1 = *(float2*)&acc2[ip][1];
        float2 q2 = *(float2*)&acc2[ip][2];
        float2 q3 = *(float2*)&acc2[ip][3];
        float2 q4 = *(float2*)&acc2[ip][4];
        float2 q5 = *(float2*)&acc2[ip][5];
        float2 q6 = *(float2*)&acc2[ip][6];
        float2 q7 = *(float2*)&acc2[ip][7];
        size_t rowA = (size_t)(m0 + r0) * N + n0;
        size_t rowB = rowA + N;
        *(float4*)&Out[rowA + tx*4]      = make_float4(q0.x, q1.x, q2.x, q3.x);
        *(float4*)&Out[rowA + 64 + tx*4] = make_float4(q4.x, q5.x, q6.x, q7.x);
        *(float4*)&Out[rowB + tx*4]      = make_float4(q0.y, q1.y, q2.y, q3.y);
        *(float4*)&Out[rowB + 64 + tx*4] = make_float4(q4.y, q5.y, q6.y, q7.y);
    }
}

// =============================================================================
//  Small GEMM (64x64, 4x4 micro) for x_proj / dt_proj
// =============================================================================
template<int EPI, bool AKMAJ, int ASRC>
__global__ __launch_bounds__(256)
void gemm_k(const float* __restrict__ W, int M, int N, int K, int lda,
            const float* __restrict__ bias)
{
    const float* A = (ASRC == 1) ? g_hid_t : g_ssm;

    __shared__ __align__(16) float As[16][68];
    __shared__ __align__(16) float Bs[16][68];

    int tid = threadIdx.x;
    int n0 = blockIdx.x * 64;
    int m0 = blockIdx.y * 64;
    int tr = tid >> 4;
    int tc = tid & 15;
    float acc[4][4] = {};

    for (int k0 = 0; k0 < K; k0 += 16) {
        if (AKMAJ) {
            #pragma unroll
            for (int i = 0; i < 4; i++) {
                int li = tid + i * 256;
                int m = li & 63, k = li >> 6;
                int gm = m0 + m;
                As[k][m] = A[(((gm >> 10) * K) + k0 + k) * L_ + (gm & 1023)];
            }
        } else {
            #pragma unroll
            for (int i = 0; i < 4; i++) {
                int li = tid + i * 256;
                int k = li & 15, m = li >> 4;
                As[k][m] = A[(m0 + m) * lda + k0 + k];
            }
        }
        #pragma unroll
        for (int i = 0; i < 4; i++) {
            int li = tid + i * 256;
            int k = li & 15, n = li >> 4;
            int gn = n0 + n;
            Bs[k][n] = (gn < N) ? W[gn * K + k0 + k] : 0.f;
        }
        __syncthreads();
        #pragma unroll
        for (int k = 0; k < 16; k++) {
            float4 av = *(const float4*)&As[k][tr * 4];
            float4 bv = *(const float4*)&Bs[k][tc * 4];
            float a4[4] = {av.x, av.y, av.z, av.w};
            float b4[4] = {bv.x, bv.y, bv.z, bv.w};
            #pragma unroll
            for (int i = 0; i < 4; i++)
                #pragma unroll
                for (int j = 0; j < 4; j++)
                    acc[i][j] = fmaf(a4[i], b4[j], acc[i][j]);
        }
        __syncthreads();
    }

    if (EPI == 1) {
        #pragma unroll
        for (int i = 0; i < 4; i++) {
            int gm = m0 + tr * 4 + i;
            #pragma unroll
            for (int j = 0; j < 4; j++) {
                int gn = n0 + tc * 4 + j;
                if (gn < N) g_ssm[gm * 96 + gn] = acc[i][j];
            }
        }
    } else {
        // dt_proj: softplus(acc + bias), store (b,d,t) with float4 along t
        int bb = m0 >> 10;
        int t0 = (m0 & 1023) + tr * 4;
        #pragma unroll
        for (int j = 0; j < 4; j++) {
            int gn = n0 + tc * 4 + j;
            float bz = bias[gn];
            float4 v;
            v.x = softplusf(acc[0][j] + bz);
            v.y = softplusf(acc[1][j] + bz);
            v.z = softplusf(acc[2][j] + bz);
            v.w = softplusf(acc[3][j] + bz);
            *(float4*)&g_dt_t[((size_t)bb * DI + gn) * L_ + t0] = v;
        }
    }
}

// =============================================================================
//  Fused chunked bidirectional scan: block = one (b,d), 8 warps = 8 chunks.
//  fwd: s_t = a_t s_{t-1} + u_t ; bwd: s_t = a_{t+1} s_{t+1} + u_t (a_L := 0)
// =============================================================================
__global__ __launch_bounds__(256)
void scan_fused(const float* __restrict__ A_log, const float* __restrict__ Dp)
{
    __shared__ float sP  [2][NS][CH];
    __shared__ float sS  [2][NS][CH];
    __shared__ float sCin[2][NS][CH];
    __shared__ float y0[L_];   // fwd contributions
    __shared__ float y1[L_];   // bwd contributions

    int bd   = blockIdx.x;
    int b    = bd >> 11;
    int d    = bd & (DI - 1);
    int c    = threadIdx.x >> 5;          // chunk
    int lane = threadIdx.x & 31;
    int n    = lane & 15;
    bool fw  = lane < 16;
    int dir  = fw ? 0 : 1;

    size_t off = ((size_t)b * DI + d) * L_;
    const float* dtp = g_dt_t  + off;
    const float* hp  = g_hid_t + off;
    const float* ssm = g_ssm   + (size_t)b * L_ * 96;
    float An = -__expf(A_log[d * NS + n]);

    int lo = c * CT, hi = lo + CT - 1;
    int sdelta = fw ? 96 : -96;

    // -------- phase A: chunk operator (P, S) --------
    {
        float s = 0.f, P = 1.f;
        float pb = (hi + 1 < L_) ? __expf(An * dtp[hi + 1]) : 0.f;
        const float* sp = ssm + (fw ? lo : hi) * 96 + 64 + n;
        for (int i0 = 0; i0 < CT; i0 += 4) {
            int tb = fw ? lo + i0 : hi - i0 - 3;
            float4 dt4 = *(const float4*)&dtp[tb];
            float4 h4  = *(const float4*)&hp[tb];
            float dts[4] = {dt4.x, dt4.y, dt4.z, dt4.w};
            float hs4[4] = {h4.x, h4.y, h4.z, h4.w};
            #pragma unroll
            for (int j = 0; j < 4; j++) {
                int jj = fw ? j : 3 - j;
                float dtv = dts[jj], h = hs4[jj];
                float a  = __expf(An * dtv);
                float Bv = sp[0];
                float u  = dtv * Bv * h;
                float coef = fw ? a : pb;
                s = fmaf(coef, s, u);
                P *= coef;
                pb = a;
                sp += sdelta;
            }
        }
        sP[dir][n][c] = P;
        sS[dir][n][c] = s;
    }
    __syncthreads();

    // -------- combine: 32 threads, one (dir, n) chain each --------
    if (threadIdx.x < 32) {
        int dr = threadIdx.x >> 4, nn = threadIdx.x & 15;
        float cin = 0.f;
        if (dr == 0) {
            #pragma unroll
            for (int cc = 0; cc < CH; cc++) {
                sCin[0][nn][cc] = cin;
                cin = fmaf(sP[0][nn][cc], cin, sS[0][nn][cc]);
            }
        } else {
            #pragma unroll
            for (int cc = CH - 1; cc >= 0; cc--) {
                sCin[1][nn][cc] = cin;
                cin = fmaf(sP[1][nn][cc], cin, sS[1][nn][cc]);
            }
        }
    }
    __syncthreads();

    // -------- phase C: seeded re-scan + multi-value shuffle reduction --------
    {
        float s  = sCin[dir][n][c];
        float pb = (hi + 1 < L_) ? __expf(An * dtp[hi + 1]) : 0.f;
        const float* sp = ssm + (fw ? lo : hi) * 96 + 64 + n;
        float* yarr = fw ? y0 : y1;
        int vsel = n >> 2;        // which of the 4 block-values this lane finishes
        int psel = n & 3;         // partial-quad index
        for (int i0 = 0; i0 < CT; i0 += 4) {
            int tb = fw ? lo + i0 : hi - i0 - 3;    // ascending-t base of this 4-block
            float4 dt4 = *(const float4*)&dtp[tb];
            float4 h4  = *(const float4*)&hp[tb];
            float dts[4] = {dt4.x, dt4.y, dt4.z, dt4.w};
            float hs4[4] = {h4.x, h4.y, h4.z, h4.w};
            float v[4];
            #pragma unroll
            for (int j = 0; j < 4; j++) {
                int jj = fw ? j : 3 - j;            // memory index within block
                float dtv = dts[jj], h = hs4[jj];
                float a  = __expf(An * dtv);
                float Bv = sp[0];
                float Cv = sp[16];
                float u  = dtv * Bv * h;
                float coef = fw ? a : pb;
                s = fmaf(coef, s, u);
                float base = fw ? s : (s - u);      // bwd contributes s_bwd - u
                v[jj] = Cv * base;                  // v indexed by ascending t
                pb = a;
                sp += sdelta;
            }
            // joint reduction of v[0..3] over the 16-lane half
            #pragma unroll
            for (int i = 0; i < 4; i++) {
                v[i] += __shfl_xor_sync(0xffffffffu, v[i], 8);
                v[i] += __shfl_xor_sync(0xffffffffu, v[i], 4);
            }
            float w = (vsel == 0) ? v[0] : (vsel == 1) ? v[1] : (vsel == 2) ? v[2] : v[3];
            w += __shfl_xor_sync(0xffffffffu, w, 2);
            w += __shfl_xor_sync(0xffffffffu, w, 1);
            if (psel == 0) yarr[tb + vsel] = w;     // 4 writers, 4 slots
        }
    }
    __syncthreads();

    // -------- epilogue: gating, vectorized --------
    {
        float Dv = Dp[d];
        int t4 = threadIdx.x * 4;
        float4 g4 = *(const float4*)&g_gate_t[off + t4];
        float4 h4 = *(const float4*)&hp[t4];
        float4 ya = *(const float4*)&y0[t4];
        float4 yb = *(const float4*)&y1[t4];
        float4 o;
        o.x = (1.3f * (ya.x + yb.x) + h4.x * Dv) * (g4.x / (1.f + __expf(-g4.x)));
        o.y = (1.3f * (ya.y + yb.y) + h4.y * Dv) * (g4.y / (1.f + __expf(-g4.y)));
        o.z = (1.3f * (ya.z + yb.z) + h4.z * Dv) * (g4.z / (1.f + __expf(-g4.z)));
        o.w = (1.3f * (ya.w + yb.w) + h4.w * Dv) * (g4.w / (1.f + __expf(-g4.w)));
        *(float4*)&g_so_t[off + t4] = o;
    }
}

// ---------------- launch -----------------------------------------------------
extern "C" void kernel_launch(void* const* d_in, const int* in_sizes, int n_in,
                              void* d_out, int out_size)
{
    const float* x      = (const float*)d_in[0];  // (2,1024,1024)
    const float* w_in   = (const float*)d_in[1];  // (4096,1024)
    const float* w_x    = (const float*)d_in[2];  // (96,2048)
    const float* w_dt   = (const float*)d_in[3];  // (2048,64)
    const float* b_dt   = (const float*)d_in[4];  // (2048,)
    const float* A_log  = (const float*)d_in[5];  // (2048,16)
    const float* Dvec   = (const float*)d_in[6];  // (2048,)
    const float* w_out  = (const float*)d_in[7];  // (1024,2048)
    float* out = (float*)d_out;                   // (2,1024,1024)

    const int M = BB * L_;  // 2048

    // 1) in_proj (packed-FMA GEMM, register-dup)
    gemm_in<<<dim3(4096 / 128, M / 128), 256>>>(x, w_in);
    // 2) x_proj: hidden (K-major) @ (96x2048)^T -> g_ssm
    gemm_k<1, true, 1><<<dim3(2, M / 64), 256>>>(w_x, M, 96, DI, 0, nullptr);
    // 3) dt_proj: ssm[:, :64] @ (2048x64)^T + b, softplus -> g_dt_t
    gemm_k<2, false, 2><<<dim3(DI / 64, M / 64), 256>>>(w_dt, M, DI, DR, 96, b_dt);
    // 4) fused chunked bidirectional scan
    scan_fused<<<BB * DI, 256>>>(A_log, Dvec);
    // 5) out_proj (packed-FMA GEMM)
    gemm_out<<<dim3(DM / 128, M / 128), 256>>>(w_out, out);
}

// round 10
// speedup vs baseline: 1.6941x; 1.3666x over previous
#include <cuda_runtime.h>
#include <cuda_bf16.h>

#define L_  1024
#define DM  1024
#define DI  2048
#define NS  16
#define DR  64
#define BB  2
#define CH  8
#define CT  (L_/CH)                 // 128 steps per chunk

typedef unsigned int        u32;
typedef unsigned long long  u64;

// ---------------- scratch (static device globals; no allocation) -------------
__device__ float g_hid_t [BB*DI*L_];   // hidden, (b, d, t)
__device__ float g_gate_t[BB*DI*L_];   // gate,   (b, d, t)
__device__ float g_ssm   [BB*L_*96];   // (b*t, 96): [0:64)=dt_pre, [64:80)=B, [80:96)=C
__device__ float g_dt_t  [BB*DI*L_];   // softplus(dt), (b, d, t)
__device__ u32   g_x_pk  [BB*L_*DM];   // x packed bf16 (hi|lo<<16), row-major (m, k)
__device__ u32   g_win_pk[2*DI*DM];    // w_in packed, (n, k)
__device__ u32   g_wout_pk[DM*DI];     // w_out packed, (n, k)
__device__ u32   g_so_pk [BB*L_*DI];   // scan output packed, (b, t, d) = (m, k)

__device__ __forceinline__ float softplusf(float x) {
    return x > 20.f ? x : log1pf(__expf(x));
}
__device__ __forceinline__ u32 pack_split(float v) {
    __nv_bfloat16 h = __float2bfloat16_rn(v);
    float hf = __bfloat162float(h);
    __nv_bfloat16 l = __float2bfloat16_rn(v - hf);
    return (u32)__bfloat16_as_ushort(h) | ((u32)__bfloat16_as_ushort(l) << 16);
}
__device__ __forceinline__ u32 smem_u32(const void* p) {
    u32 a;
    asm("{ .reg .u64 t; cvta.to.shared.u64 t, %1; cvt.u32.u64 %0, t; }" : "=r"(a) : "l"(p));
    return a;
}
__device__ __forceinline__ void ldm_x4(u32& r0, u32& r1, u32& r2, u32& r3, u32 addr) {
    asm volatile("ldmatrix.sync.aligned.m8n8.x4.shared.b16 {%0,%1,%2,%3}, [%4];"
                 : "=r"(r0), "=r"(r1), "=r"(r2), "=r"(r3) : "r"(addr));
}
__device__ __forceinline__ void mma_bf16(float* c, const u32* a, u32 b0, u32 b1) {
    asm volatile("mma.sync.aligned.m16n8k16.row.col.f32.bf16.bf16.f32 "
                 "{%0,%1,%2,%3}, {%4,%5,%6,%7}, {%8,%9}, {%0,%1,%2,%3};"
                 : "+f"(c[0]), "+f"(c[1]), "+f"(c[2]), "+f"(c[3])
                 : "r"(a[0]), "r"(a[1]), "r"(a[2]), "r"(a[3]), "r"(b0), "r"(b1));
}

// =============================================================================
//  bf16x3 split GEMM on mma.sync: CTA tile 128x128, BK=32, 8 warps (4x2),
//  warp tile 32x64.  C = Ah*Bh + Ah*Bl + Al*Bh  (fp32 accum; drop Al*Bl).
//  smem stage: Ah[128][40]bf16, Al, Bh, Bl  (rows padded to 80B: 16B-aligned,
//  20-word stride permutes ldmatrix row-addresses conflict-free).
// =============================================================================
#define ROWB    80                     // padded row bytes (32 bf16 + 8 pad)
#define MATB    (128*ROWB)             // 10240 per matrix
#define STAGEB  (4*MATB)               // Ah, Al, Bh, Bl
#define DYN_SMEM (2*STAGEB)            // 81920

__device__ __forceinline__ void st_frag(char* base, int row, int c4, uint4 v) {
    u32 h0 = __byte_perm(v.x, v.y, 0x5410);
    u32 h1 = __byte_perm(v.z, v.w, 0x5410);
    u32 l0 = __byte_perm(v.x, v.y, 0x7632);
    u32 l1 = __byte_perm(v.z, v.w, 0x7632);
    *(uint2*)(base + row * ROWB + c4 * 8)        = make_uint2(h0, h1);
    *(uint2*)(base + MATB + row * ROWB + c4 * 8) = make_uint2(l0, l1);
}

// EPI 0: in_proj (A=g_x_pk, B=g_win_pk) -> transposed split write hid/gate (b,d,t)
// EPI 1: out_proj (A=g_so_pk, B=g_wout_pk) -> row-major Out
template<int EPI>
__global__ void __launch_bounds__(256) gemm_mma(int Kfull, float* __restrict__ Out)
{
    const u32* Apk = (EPI == 0) ? g_x_pk   : g_so_pk;
    const u32* Bpk = (EPI == 0) ? g_win_pk : g_wout_pk;

    extern __shared__ __align__(16) char sm[];
    u32 smb = smem_u32(sm);

    int tid = threadIdx.x;
    int lane = tid & 31, wid = tid >> 5;
    int wm = wid >> 1, wn = wid & 1;
    int n0 = blockIdx.x * 128;
    int m0 = blockIdx.y * 128;

    float acc[2][8][4] = {};

    const int nch = Kfull / 32;
    int arow[4], ac4[4];
    #pragma unroll
    for (int r = 0; r < 4; r++) {
        int li = tid + r * 256;
        arow[r] = li >> 3;       // 0..127
        ac4[r]  = li & 7;        // uint4 index within 32-k chunk
    }

    // load + store chunk 0
    {
        #pragma unroll
        for (int r = 0; r < 4; r++) {
            uint4 va = *(const uint4*)&Apk[(size_t)(m0 + arow[r]) * Kfull + ac4[r] * 4];
            uint4 vb = *(const uint4*)&Bpk[(size_t)(n0 + arow[r]) * Kfull + ac4[r] * 4];
            st_frag(sm, arow[r], ac4[r], va);
            st_frag(sm + 2 * MATB, arow[r], ac4[r], vb);
        }
    }
    __syncthreads();

    int rl = lane & 15, kh = lane >> 4;   // ldmatrix row-lane / k-half

    for (int i = 0; i < nch; i++) {
        int p = i & 1;
        bool pf = (i + 1) < nch;
        uint4 na[4], nb[4];
        if (pf) {
            int k0 = (i + 1) * 8;  // in uint4 units: (i+1)*32/4
            #pragma unroll
            for (int r = 0; r < 4; r++) {
                na[r] = *(const uint4*)&Apk[(size_t)(m0 + arow[r]) * Kfull + (k0 + ac4[r]) * 4];
                nb[r] = *(const uint4*)&Bpk[(size_t)(n0 + arow[r]) * Kfull + (k0 + ac4[r]) * 4];
            }
        }

        // ---- compute on stage p ----
        u32 sb = smb + p * STAGEB;
        #pragma unroll
        for (int kk = 0; kk < 2; kk++) {
            int kcolb = (kk * 16 + kh * 8) * 2;   // byte offset of k column
            u32 ah[2][4], al[2][4];
            #pragma unroll
            for (int mi = 0; mi < 2; mi++) {
                u32 addr = sb + (u32)((wm * 32 + mi * 16 + rl) * ROWB + kcolb);
                ldm_x4(ah[mi][0], ah[mi][1], ah[mi][2], ah[mi][3], addr);
                ldm_x4(al[mi][0], al[mi][1], al[mi][2], al[mi][3], addr + MATB);
            }
            #pragma unroll
            for (int nj2 = 0; nj2 < 4; nj2++) {
                u32 addr = sb + 2 * MATB + (u32)((wn * 64 + nj2 * 16 + rl) * ROWB + kcolb);
                u32 bh[4], bl[4];
                ldm_x4(bh[0], bh[1], bh[2], bh[3], addr);
                ldm_x4(bl[0], bl[1], bl[2], bl[3], addr + MATB);
                #pragma unroll
                for (int mi = 0; mi < 2; mi++) {
                    #pragma unroll
                    for (int o = 0; o < 2; o++) {
                        float* c = acc[mi][nj2 * 2 + o];
                        mma_bf16(c, ah[mi], bh[o], bh[o + 2]);
                        mma_bf16(c, ah[mi], bl[o], bl[o + 2]);
                        mma_bf16(c, al[mi], bh[o], bh[o + 2]);
                    }
                }
            }
        }

        if (pf) {
            char* q = sm + (1 - p) * STAGEB;
            #pragma unroll
            for (int r = 0; r < 4; r++) {
                st_frag(q, arow[r], ac4[r], na[r]);
                st_frag(q + 2 * MATB, arow[r], ac4[r], nb[r]);
            }
        }
        __syncthreads();
    }

    // ---- epilogue: stage C (128x132 fp32) in smem, coalesced write-out ----
    float* Cs = (float*)sm;
    {
        int tq = lane >> 2, tr2 = (lane & 3) * 2;
        #pragma unroll
        for (int mi = 0; mi < 2; mi++) {
            #pragma unroll
            for (int nj = 0; nj < 8; nj++) {
                int row = wm * 32 + mi * 16 + tq;
                int col = wn * 64 + nj * 8 + tr2;
                float* c = acc[mi][nj];
                *(float2*)&Cs[row * 132 + col]       = make_float2(c[0], c[1]);
                *(float2*)&Cs[(row + 8) * 132 + col] = make_float2(c[2], c[3]);
            }
        }
    }
    __syncthreads();

    if (EPI == 0) {
        int bb = m0 >> 10;
        int t0 = m0 & 1023;
        float* dst = (n0 < DI) ? g_hid_t : g_gate_t;
        int nb = n0 & (DI - 1);
        #pragma unroll
        for (int r = 0; r < 16; r++) {
            int li = tid + r * 256;
            int col = li & 127, mb = li >> 7;     // col 0..127, m-block 0..31
            float4 v = make_float4(Cs[(mb * 4 + 0) * 132 + col],
                                   Cs[(mb * 4 + 1) * 132 + col],
                                   Cs[(mb * 4 + 2) * 132 + col],
                                   Cs[(mb * 4 + 3) * 132 + col]);
            *(float4*)&dst[((size_t)bb * DI + nb + col) * L_ + t0 + mb * 4] = v;
        }
    } else {
        #pragma unroll
        for (int r = 0; r < 16; r++) {
            int li = tid + r * 256;
            int row = li >> 5, cb = li & 31;
            float4 v = *(float4*)&Cs[row * 132 + cb * 4];
            *(float4*)&Out[(size_t)(m0 + row) * DM + n0 + cb * 4] = v;
        }
    }
}

// ---------------- fp32 -> packed bf16-split converter ------------------------
template<int DST>
__global__ void cvt_pack(const float* __restrict__ in, int n4)
{
    u32* out = (DST == 0) ? g_x_pk : (DST == 1) ? g_win_pk : g_wout_pk;
    int i = blockIdx.x * blockDim.x + threadIdx.x;
    if (i < n4) {
        float4 v = ((const float4*)in)[i];
        uint4 o;
        o.x = pack_split(v.x); o.y = pack_split(v.y);
        o.z = pack_split(v.z); o.w = pack_split(v.w);
        ((uint4*)out)[i] = o;
    }
}

// =============================================================================
//  Small GEMM (64x64, 4x4 micro) for x_proj / dt_proj  (FFMA)
// =============================================================================
template<int EPI, bool AKMAJ, int ASRC>
__global__ __launch_bounds__(256)
void gemm_k(const float* __restrict__ W, int M, int N, int K, int lda,
            const float* __restrict__ bias)
{
    const float* A = (ASRC == 1) ? g_hid_t : g_ssm;

    __shared__ __align__(16) float As[16][68];
    __shared__ __align__(16) float Bs[16][68];

    int tid = threadIdx.x;
    int n0 = blockIdx.x * 64;
    int m0 = blockIdx.y * 64;
    int tr = tid >> 4;
    int tc = tid & 15;
    float acc[4][4] = {};

    for (int k0 = 0; k0 < K; k0 += 16) {
        if (AKMAJ) {
            #pragma unroll
            for (int i = 0; i < 4; i++) {
                int li = tid + i * 256;
                int m = li & 63, k = li >> 6;
                int gm = m0 + m;
                As[k][m] = A[(((gm >> 10) * K) + k0 + k) * L_ + (gm & 1023)];
            }
        } else {
            #pragma unroll
            for (int i = 0; i < 4; i++) {
                int li = tid + i * 256;
                int k = li & 15, m = li >> 4;
                As[k][m] = A[(m0 + m) * lda + k0 + k];
            }
        }
        #pragma unroll
        for (int i = 0; i < 4; i++) {
            int li = tid + i * 256;
            int k = li & 15, n = li >> 4;
            int gn = n0 + n;
            Bs[k][n] = (gn < N) ? W[gn * K + k0 + k] : 0.f;
        }
        __syncthreads();
        #pragma unroll
        for (int k = 0; k < 16; k++) {
            float4 av = *(const float4*)&As[k][tr * 4];
            float4 bv = *(const float4*)&Bs[k][tc * 4];
            float a4[4] = {av.x, av.y, av.z, av.w};
            float b4[4] = {bv.x, bv.y, bv.z, bv.w};
            #pragma unroll
            for (int i = 0; i < 4; i++)
                #pragma unroll
                for (int j = 0; j < 4; j++)
                    acc[i][j] = fmaf(a4[i], b4[j], acc[i][j]);
        }
        __syncthreads();
    }

    if (EPI == 1) {
        #pragma unroll
        for (int i = 0; i < 4; i++) {
            int gm = m0 + tr * 4 + i;
            #pragma unroll
            for (int j = 0; j < 4; j++) {
                int gn = n0 + tc * 4 + j;
                if (gn < N) g_ssm[gm * 96 + gn] = acc[i][j];
            }
        }
    } else {
        int bb = m0 >> 10;
        int t0 = (m0 & 1023) + tr * 4;
        #pragma unroll
        for (int j = 0; j < 4; j++) {
            int gn = n0 + tc * 4 + j;
            float bz = bias[gn];
            float4 v;
            v.x = softplusf(acc[0][j] + bz);
            v.y = softplusf(acc[1][j] + bz);
            v.z = softplusf(acc[2][j] + bz);
            v.w = softplusf(acc[3][j] + bz);
            *(float4*)&g_dt_t[((size_t)bb * DI + gn) * L_ + t0] = v;
        }
    }
}

// =============================================================================
//  Fused chunked bidirectional scan (epilogue writes packed so (b,t,d))
// =============================================================================
__global__ __launch_bounds__(256)
void scan_fused(const float* __restrict__ A_log, const float* __restrict__ Dp)
{
    __shared__ float sP  [2][NS][CH];
    __shared__ float sS  [2][NS][CH];
    __shared__ float sCin[2][NS][CH];
    __shared__ float y0[L_];   // fwd contributions
    __shared__ float y1[L_];   // bwd contributions

    int bd   = blockIdx.x;
    int b    = bd >> 11;
    int d    = bd & (DI - 1);
    int c    = threadIdx.x >> 5;          // chunk
    int lane = threadIdx.x & 31;
    int n    = lane & 15;
    bool fw  = lane < 16;
    int dir  = fw ? 0 : 1;

    size_t off = ((size_t)b * DI + d) * L_;
    const float* dtp = g_dt_t  + off;
    const float* hp  = g_hid_t + off;
    const float* ssm = g_ssm   + (size_t)b * L_ * 96;
    float An = -__expf(A_log[d * NS + n]);

    int lo = c * CT, hi = lo + CT - 1;
    int sdelta = fw ? 96 : -96;

    // -------- phase A: chunk operator (P, S) --------
    {
        float s = 0.f, P = 1.f;
        float pb = (hi + 1 < L_) ? __expf(An * dtp[hi + 1]) : 0.f;
        const float* sp = ssm + (fw ? lo : hi) * 96 + 64 + n;
        for (int i0 = 0; i0 < CT; i0 += 4) {
            int tb = fw ? lo + i0 : hi - i0 - 3;
            float4 dt4 = *(const float4*)&dtp[tb];
            float4 h4  = *(const float4*)&hp[tb];
            float dts[4] = {dt4.x, dt4.y, dt4.z, dt4.w};
            float hs4[4] = {h4.x, h4.y, h4.z, h4.w};
            #pragma unroll
            for (int j = 0; j < 4; j++) {
                int jj = fw ? j : 3 - j;
                float dtv = dts[jj], h = hs4[jj];
                float a  = __expf(An * dtv);
                float Bv = sp[0];
                float u  = dtv * Bv * h;
                float coef = fw ? a : pb;
                s = fmaf(coef, s, u);
                P *= coef;
                pb = a;
                sp += sdelta;
            }
        }
        sP[dir][n][c] = P;
        sS[dir][n][c] = s;
    }
    __syncthreads();

    // -------- combine: 32 threads, one (dir, n) chain each --------
    if (threadIdx.x < 32) {
        int dr = threadIdx.x >> 4, nn = threadIdx.x & 15;
        float cin = 0.f;
        if (dr == 0) {
            #pragma unroll
            for (int cc = 0; cc < CH; cc++) {
                sCin[0][nn][cc] = cin;
                cin = fmaf(sP[0][nn][cc], cin, sS[0][nn][cc]);
            }
        } else {
            #pragma unroll
            for (int cc = CH - 1; cc >= 0; cc--) {
                sCin[1][nn][cc] = cin;
                cin = fmaf(sP[1][nn][cc], cin, sS[1][nn][cc]);
            }
        }
    }
    __syncthreads();

    // -------- phase C: seeded re-scan + multi-value shuffle reduction --------
    {
        float s  = sCin[dir][n][c];
        float pb = (hi + 1 < L_) ? __expf(An * dtp[hi + 1]) : 0.f;
        const float* sp = ssm + (fw ? lo : hi) * 96 + 64 + n;
        float* yarr = fw ? y0 : y1;
        int vsel = n >> 2;
        int psel = n & 3;
        for (int i0 = 0; i0 < CT; i0 += 4) {
            int tb = fw ? lo + i0 : hi - i0 - 3;
            float4 dt4 = *(const float4*)&dtp[tb];
            float4 h4  = *(const float4*)&hp[tb];
            float dts[4] = {dt4.x, dt4.y, dt4.z, dt4.w};
            float hs4[4] = {h4.x, h4.y, h4.z, h4.w};
            float v[4];
            #pragma unroll
            for (int j = 0; j < 4; j++) {
                int jj = fw ? j : 3 - j;
                float dtv = dts[jj], h = hs4[jj];
                float a  = __expf(An * dtv);
                float Bv = sp[0];
                float Cv = sp[16];
                float u  = dtv * Bv * h;
                float coef = fw ? a : pb;
                s = fmaf(coef, s, u);
                float base = fw ? s : (s - u);
                v[jj] = Cv * base;
                pb = a;
                sp += sdelta;
            }
            #pragma unroll
            for (int i = 0; i < 4; i++) {
                v[i] += __shfl_xor_sync(0xffffffffu, v[i], 8);
                v[i] += __shfl_xor_sync(0xffffffffu, v[i], 4);
            }
            float w = (vsel == 0) ? v[0] : (vsel == 1) ? v[1] : (vsel == 2) ? v[2] : v[3];
            w += __shfl_xor_sync(0xffffffffu, w, 2);
            w += __shfl_xor_sync(0xffffffffu, w, 1);
            if (psel == 0) yarr[tb + vsel] = w;
        }
    }
    __syncthreads();

    // -------- epilogue: gating -> packed bf16-split so, (b, t, d) layout -----
    {
        float Dv = Dp[d];
        int t4 = threadIdx.x * 4;
        float4 g4 = *(const float4*)&g_gate_t[off + t4];
        float4 h4 = *(const float4*)&hp[t4];
        float4 ya = *(const float4*)&y0[t4];
        float4 yb = *(const float4*)&y1[t4];
        float4 o;
        o.x = (1.3f * (ya.x + yb.x) + h4.x * Dv) * (g4.x / (1.f + __expf(-g4.x)));
        o.y = (1.3f * (ya.y + yb.y) + h4.y * Dv) * (g4.y / (1.f + __expf(-g4.y)));
        o.z = (1.3f * (ya.z + yb.z) + h4.z * Dv) * (g4.z / (1.f + __expf(-g4.z)));
        o.w = (1.3f * (ya.w + yb.w) + h4.w * Dv) * (g4.w / (1.f + __expf(-g4.w)));
        u32* sop = g_so_pk + (size_t)b * L_ * DI + d;
        sop[(size_t)(t4 + 0) * DI] = pack_split(o.x);
        sop[(size_t)(t4 + 1) * DI] = pack_split(o.y);
        sop[(size_t)(t4 + 2) * DI] = pack_split(o.z);
        sop[(size_t)(t4 + 3) * DI] = pack_split(o.w);
    }
}

// ---------------- launch -----------------------------------------------------
extern "C" void kernel_launch(void* const* d_in, const int* in_sizes, int n_in,
                              void* d_out, int out_size)
{
    const float* x      = (const float*)d_in[0];  // (2,1024,1024)
    const float* w_in   = (const float*)d_in[1];  // (4096,1024)
    const float* w_x    = (const float*)d_in[2];  // (96,2048)
    const float* w_dt   = (const float*)d_in[3];  // (2048,64)
    const float* b_dt   = (const float*)d_in[4];  // (2048,)
    const float* A_log  = (const float*)d_in[5];  // (2048,16)
    const float* Dvec   = (const float*)d_in[6];  // (2048,)
    const float* w_out  = (const float*)d_in[7];  // (1024,2048)
    float* out = (float*)d_out;                   // (2,1024,1024)

    const int M = BB * L_;  // 2048

    cudaFuncSetAttribute(gemm_mma<0>, cudaFuncAttributeMaxDynamicSharedMemorySize, DYN_SMEM);
    cudaFuncSetAttribute(gemm_mma<1>, cudaFuncAttributeMaxDynamicSharedMemorySize, DYN_SMEM);

    // 0) pack inputs to bf16 hi/lo
    cvt_pack<0><<<(BB*L_*DM/4 + 255)/256, 256>>>(x,     BB*L_*DM/4);
    cvt_pack<1><<<(2*DI*DM/4  + 255)/256, 256>>>(w_in,  2*DI*DM/4);
    cvt_pack<2><<<(DM*DI/4    + 255)/256, 256>>>(w_out, DM*DI/4);

    // 1) in_proj (mma.sync bf16x3) -> hid/gate (b,d,t)
    gemm_mma<0><<<dim3(2*DI/128, M/128), 256, DYN_SMEM>>>(DM, nullptr);
    // 2) x_proj: hidden (K-major) @ (96x2048)^T -> g_ssm
    gemm_k<1, true, 1><<<dim3(2, M/64), 256>>>(w_x, M, 96, DI, 0, nullptr);
    // 3) dt_proj: ssm[:, :64] @ (2048x64)^T + b, softplus -> g_dt_t
    gemm_k<2, false, 2><<<dim3(DI/64, M/64), 256>>>(w_dt, M, DI, DR, 96, b_dt);
    // 4) fused chunked bidirectional scan (writes packed so)
    scan_fused<<<BB * DI, 256>>>(A_log, Dvec);
    // 5) out_proj (mma.sync bf16x3)
    gemm_mma<1><<<dim3(DM/128, M/128), 256, DYN_SMEM>>>(DI, out);
}